// round 7
// baseline (speedup 1.0000x reference)
#include <cuda_runtime.h>
#include <math.h>
#include <stdint.h>

// Problem dims
#define Bsz 512
#define Ssz 10
#define Tsz 10
#define Esz 512
#define Hsz 512          // HB = HD
#define Dsz 1024         // dec hidden = HB + HD
#define Psz 512          // predictor input
#define PDsz 4
#define NROWS (Ssz*Bsz)  // 5120
#define G3H (3*Hsz)      // 1536
#define G3D (3*Dsz)      // 3072

#define KB 16            // k-elements per pipeline stage
#define STR 40           // smem floats per row: 16 elems x2 (hi,lo) + 8 pad

// ---------------- scratch (hi/lo interleaved planes marked I) ----------------
__device__ float g_embI[2][NROWS*Esz*2];
__device__ float g_gi[2][NROWS*G3H];
__device__ float g_hbufI[2][2][Bsz*Hsz*2];
__device__ float g_H[2][NROWS*Dsz];
__device__ float g_HI[2][NROWS*Dsz*2];
__device__ float g_PII[NROWS*Psz*2];
__device__ float g_WihI[2][G3H*Esz*2];
__device__ float g_WhhI[2][G3H*Hsz*2];
__device__ float g_WihDecI[G3D*Psz*2];
__device__ float g_WhhDecI[(size_t)G3D*Dsz*2];
__device__ float g_WpiTI[Psz*Dsz*2];

__device__ __forceinline__ float sigmf(float x) { return 1.0f / (1.0f + __expf(-x)); }

__device__ __forceinline__ void split2(float v, float& hi, float& lo) {
    uint32_t h;
    asm("cvt.rna.tf32.f32 %0, %1;" : "=r"(h) : "f"(v));
    float hf = __uint_as_float(h);
    hi = hf; lo = v - hf;
}

__device__ __forceinline__ void mma8(float* c, const uint32_t* a, const uint32_t* b) {
    asm("mma.sync.aligned.m16n8k8.row.col.f32.tf32.tf32.f32 "
        "{%0,%1,%2,%3}, {%4,%5,%6,%7}, {%8,%9}, {%0,%1,%2,%3};"
        : "+f"(c[0]), "+f"(c[1]), "+f"(c[2]), "+f"(c[3])
        : "r"(a[0]), "r"(a[1]), "r"(a[2]), "r"(a[3]), "r"(b[0]), "r"(b[1]));
}

__device__ __forceinline__ void cpa16(void* smem_ptr, const void* gptr) {
    uint32_t s = (uint32_t)__cvta_generic_to_shared(smem_ptr);
    asm volatile("cp.async.cg.shared.global [%0], [%1], 16;" :: "r"(s), "l"(gptr));
}
#define CPA_COMMIT asm volatile("cp.async.commit_group;")
#define CPA_WAIT1  asm volatile("cp.async.wait_group 1;")
#define CPA_WAIT0  asm volatile("cp.async.wait_group 0;")

// pack fp32 v into interleaved float4 slots (x=hi0,y=lo0,z=hi1,w=lo1)
__device__ __forceinline__ float4 pack2(float vx, float vy) {
    float4 o;
    split2(vx, o.x, o.y);
    split2(vy, o.z, o.w);
    return o;
}

// ---------------- one-time splits ----------------
__global__ void split_kernel(const float* __restrict__ in, float* __restrict__ out, int n)
{
    int i = blockIdx.x * blockDim.x + threadIdx.x;
    if (i >= n) return;
    float hi, lo; split2(in[i], hi, lo);
    *(float2*)(out + (size_t)i * 2) = make_float2(hi, lo);
}

// W_h2pi [D][P] -> interleaved [P][2D]
__global__ void transpose_split_kernel(const float* __restrict__ W, float* __restrict__ WT2)
{
    __shared__ float t[32][33];
    int bx = blockIdx.x * 32, by = blockIdx.y * 32;
    int x = threadIdx.x, y = threadIdx.y;
#pragma unroll
    for (int i = 0; i < 32; i += 8) t[y + i][x] = W[(size_t)(by + y + i) * Psz + bx + x];
    __syncthreads();
#pragma unroll
    for (int i = 0; i < 32; i += 8) {
        float hi, lo; split2(t[x][y + i], hi, lo);
        *(float2*)(WT2 + ((size_t)(bx + y + i) * Dsz + by + x) * 2) = make_float2(hi, lo);
    }
}

// ---------------- embeddings: relu(x @ W + b), K=4, interleaved out ----------------
__global__ void embed_kernel(const float* __restrict__ box, const float* __restrict__ dm,
                             const float* __restrict__ Wb, const float* __restrict__ bb,
                             const float* __restrict__ Wd, const float* __restrict__ bd)
{
    int idx = blockIdx.x * blockDim.x + threadIdx.x;
    if (idx >= NROWS * Esz) return;
    int e = idx % Esz;
    int sb = idx / Esz;
    int b = sb % Bsz, s = sb / Bsz;
    const float* x; const float* W; const float* bi; float* out;
    if (blockIdx.y == 0) { x = box; W = Wb; bi = bb; out = g_embI[0]; }
    else                 { x = dm;  W = Wd; bi = bd; out = g_embI[1]; }
    const float* xp = x + ((size_t)b * Ssz + s) * 4;
    float acc = bi[e];
#pragma unroll
    for (int k = 0; k < 4; k++) acc = fmaf(xp[k], W[(size_t)k * Esz + e], acc);
    acc = fmaxf(acc, 0.0f);
    float hi, lo; split2(acc, hi, lo);
    *(float2*)(out + (size_t)idx * 2) = make_float2(hi, lo);
}

// ---- fragment loads from interleaved smem ----
#define LOAD_A_FRAG(Asb, ah, al)                                             \
    _Pragma("unroll") for (int mf = 0; mf < 2; mf++) {                       \
        int mb = wm * 32 + mf * 16 + r;                                      \
        float2 p0 = ((const float2*)((Asb) + mb * STR))[kk + cq];            \
        float2 p1 = ((const float2*)((Asb) + (mb + 8) * STR))[kk + cq];      \
        float2 p2 = ((const float2*)((Asb) + mb * STR))[kk + cq + 4];        \
        float2 p3 = ((const float2*)((Asb) + (mb + 8) * STR))[kk + cq + 4];  \
        ah[mf][0] = __float_as_uint(p0.x); al[mf][0] = __float_as_uint(p0.y);\
        ah[mf][1] = __float_as_uint(p1.x); al[mf][1] = __float_as_uint(p1.y);\
        ah[mf][2] = __float_as_uint(p2.x); al[mf][2] = __float_as_uint(p2.y);\
        ah[mf][3] = __float_as_uint(p3.x); al[mf][3] = __float_as_uint(p3.y);\
    }

#define LOAD_B_FRAG(Bsb, nb, bh, bl)                                         \
    {                                                                        \
        float2 q0 = ((const float2*)((Bsb) + (nb) * STR))[kk + cq];          \
        float2 q1 = ((const float2*)((Bsb) + (nb) * STR))[kk + cq + 4];      \
        bh[0] = __float_as_uint(q0.x); bl[0] = __float_as_uint(q0.y);        \
        bh[1] = __float_as_uint(q1.x); bl[1] = __float_as_uint(q1.y);        \
    }

// ================= generic pipelined NT GEMM on interleaved planes =================
// C[M,Nn] = A[M,K] @ B[Nn,K]^T + bias.  OUTI=0: plain fp32 out. OUTI=1: relu + interleaved out.
__device__ __forceinline__ void gemm_prefetch(float* sA, float* sB,
    const float* A2, const float* B2, int K, int k0, int m0, int n0, int tid)
{
#pragma unroll
    for (int i = 0; i < 4; i++) {
        int f = tid + i * 256;            // 1024 chunks: 128 rows x 8
        int m = f >> 3, c = (f & 7) * 4;
        cpa16(sA + m * STR + c, A2 + ((size_t)(m0 + m) * K + k0) * 2 + c);
    }
#pragma unroll
    for (int i = 0; i < 2; i++) {
        int f = tid + i * 256;            // 512 chunks: 64 rows x 8
        int row = f >> 3, c = (f & 7) * 4;
        cpa16(sB + row * STR + c, B2 + ((size_t)(n0 + row) * K + k0) * 2 + c);
    }
}

template <int OUTI>
__global__ __launch_bounds__(256) void gemm_nt_pipe(
    const float* __restrict__ A2, int K,
    const float* __restrict__ B2, const float* __restrict__ bias,
    float* __restrict__ C, int Nn)
{
    extern __shared__ float smem[];
    float* sA = smem;                    // 2 x 128 x STR
    float* sB = smem + 2 * 128 * STR;    // 2 x 64 x STR
    int tid = threadIdx.x, lane = tid & 31, wid = tid >> 5;
    int wm = wid & 3, wn = wid >> 2;
    int m0 = blockIdx.y * 128, n0 = blockIdx.x * 64;
    int r = lane >> 2, cq = lane & 3;
    float acc[2][4][4] = {};

    int nstg = K / KB;
    gemm_prefetch(sA, sB, A2, B2, K, 0, m0, n0, tid);
    CPA_COMMIT;
    for (int st = 0; st < nstg; st++) {
        float* Asb = sA + (st & 1) * (128 * STR);
        float* Bsb = sB + (st & 1) * (64 * STR);
        if (st + 1 < nstg) {
            gemm_prefetch(sA + ((st + 1) & 1) * (128 * STR), sB + ((st + 1) & 1) * (64 * STR),
                          A2, B2, K, (st + 1) * KB, m0, n0, tid);
            CPA_COMMIT; CPA_WAIT1;
        } else { CPA_WAIT0; }
        __syncthreads();
#pragma unroll
        for (int kk = 0; kk < KB; kk += 8) {
            uint32_t ah[2][4], al[2][4];
            LOAD_A_FRAG(Asb, ah, al)
#pragma unroll
            for (int nf = 0; nf < 4; nf++) {
                int nb = wn * 32 + nf * 8 + r;
                uint32_t bh[2], bl[2];
                LOAD_B_FRAG(Bsb, nb, bh, bl)
#pragma unroll
                for (int mf = 0; mf < 2; mf++) {
                    mma8(acc[mf][nf], ah[mf], bh);
                    mma8(acc[mf][nf], ah[mf], bl);
                    mma8(acc[mf][nf], al[mf], bh);
                }
            }
        }
        __syncthreads();
    }
#pragma unroll
    for (int nf = 0; nf < 4; nf++) {
        int u = n0 + wn * 32 + nf * 8 + 2 * cq;
        float2 bi2 = *(const float2*)(bias + u);
#pragma unroll
        for (int mf = 0; mf < 2; mf++) {
#pragma unroll
            for (int half = 0; half < 2; half++) {
                int m = m0 + wm * 32 + mf * 16 + r + half * 8;
                float vx = acc[mf][nf][half * 2 + 0] + bi2.x;
                float vy = acc[mf][nf][half * 2 + 1] + bi2.y;
                if (OUTI == 1) {
                    vx = fmaxf(vx, 0.0f); vy = fmaxf(vy, 0.0f);
                    *(float4*)(C + ((size_t)m * Nn + u) * 2) = pack2(vx, vy);
                } else {
                    float2 o = {vx, vy};
                    *(float2*)(C + (size_t)m * Nn + u) = o;
                }
            }
        }
    }
}

// ================= encoder recurrent step =================
__device__ __forceinline__ void enc_prefetch(float* sA, float* sB,
    const float* hinI, const float* WhhI, int k0, int m0, int n0, int tid)
{
#pragma unroll
    for (int i = 0; i < 2; i++) {
        int f = tid + i * 256;            // 512: 64 rows x 8
        int m = f >> 3, c = (f & 7) * 4;
        cpa16(sA + m * STR + c, hinI + ((size_t)(m0 + m) * Hsz + k0) * 2 + c);
    }
#pragma unroll
    for (int i = 0; i < 3; i++) {
        int f = tid + i * 256;            // 768: 96 rows x 8
        int row = f >> 3, c = (f & 7) * 4;
        int g = row >> 5, nn = row & 31;
        cpa16(sB + row * STR + c, WhhI + ((size_t)(g * Hsz + n0 + nn) * Hsz + k0) * 2 + c);
    }
}

__global__ __launch_bounds__(256) void enc_step_mma(
    int s, int par,
    const float* __restrict__ bhh0, const float* __restrict__ bhh1,
    float* __restrict__ H0out, float* __restrict__ H0outI)
{
    extern __shared__ float smem[];
    float* sA = smem;                    // 2 x 64 x STR
    float* sB = smem + 2 * 64 * STR;     // 2 x 96 x STR
    int z = blockIdx.z;
    const float* WhhI = g_WhhI[z];
    const float* bhh = z ? bhh1 : bhh0;
    const float* hinI = g_hbufI[z][par];
    float* houtI = g_hbufI[z][par ^ 1];
    const float* gi = g_gi[z] + (size_t)s * Bsz * G3H;

    int tid = threadIdx.x, lane = tid & 31, wid = tid >> 5;
    int wm = wid & 1, wn = wid >> 1;
    int m0 = blockIdx.y * 64, n0 = blockIdx.x * 32;
    int r = lane >> 2, cq = lane & 3;
    float accR[2][4] = {}, accZ[2][4] = {}, accN[2][4] = {};

    int nstg = Hsz / KB;
    enc_prefetch(sA, sB, hinI, WhhI, 0, m0, n0, tid);
    CPA_COMMIT;
    for (int st = 0; st < nstg; st++) {
        float* Asb = sA + (st & 1) * (64 * STR);
        float* Bsb = sB + (st & 1) * (96 * STR);
        if (st + 1 < nstg) {
            enc_prefetch(sA + ((st + 1) & 1) * (64 * STR), sB + ((st + 1) & 1) * (96 * STR),
                         hinI, WhhI, (st + 1) * KB, m0, n0, tid);
            CPA_COMMIT; CPA_WAIT1;
        } else { CPA_WAIT0; }
        __syncthreads();
#pragma unroll
        for (int kk = 0; kk < KB; kk += 8) {
            uint32_t ah[2][4], al[2][4];
            LOAD_A_FRAG(Asb, ah, al)
#pragma unroll
            for (int g = 0; g < 3; g++) {
                int nb = g * 32 + wn * 8 + r;
                uint32_t bh[2], bl[2];
                LOAD_B_FRAG(Bsb, nb, bh, bl)
#pragma unroll
                for (int mf = 0; mf < 2; mf++) {
                    float* cc = (g == 0) ? accR[mf] : (g == 1) ? accZ[mf] : accN[mf];
                    mma8(cc, ah[mf], bh);
                    mma8(cc, ah[mf], bl);
                    mma8(cc, al[mf], bh);
                }
            }
        }
        __syncthreads();
    }
    // epilogue
    int u = n0 + wn * 8 + 2 * cq;
    float2 bR = *(const float2*)(bhh + u);
    float2 bZ = *(const float2*)(bhh + Hsz + u);
    float2 bN = *(const float2*)(bhh + 2 * Hsz + u);
#pragma unroll
    for (int mf = 0; mf < 2; mf++) {
#pragma unroll
        for (int half = 0; half < 2; half++) {
            int m = m0 + wm * 32 + mf * 16 + r + half * 8;
            float2 giR = *(const float2*)(gi + (size_t)m * G3H + u);
            float2 giZ = *(const float2*)(gi + (size_t)m * G3H + Hsz + u);
            float2 giN = *(const float2*)(gi + (size_t)m * G3H + 2 * Hsz + u);
            float4 hv = *(const float4*)(hinI + ((size_t)m * Hsz + u) * 2);
            float holdx = hv.x + hv.y, holdy = hv.z + hv.w;   // exact reconstruction
            int c0 = half * 2;
            float rx = sigmf(giR.x + accR[mf][c0 + 0] + bR.x);
            float ry = sigmf(giR.y + accR[mf][c0 + 1] + bR.y);
            float zx = sigmf(giZ.x + accZ[mf][c0 + 0] + bZ.x);
            float zy = sigmf(giZ.y + accZ[mf][c0 + 1] + bZ.y);
            float nx = tanhf(giN.x + rx * (accN[mf][c0 + 0] + bN.x));
            float ny = tanhf(giN.y + ry * (accN[mf][c0 + 1] + bN.y));
            float ox = nx + zx * (holdx - nx);
            float oy = ny + zy * (holdy - ny);
            *(float4*)(houtI + ((size_t)m * Hsz + u) * 2) = pack2(ox, oy);
            size_t hrow = (size_t)s * Bsz + m;
            *(float2*)(H0out + hrow * Dsz + (size_t)z * Hsz + u) = make_float2(ox, oy);
            *(float4*)(H0outI + (hrow * Dsz + (size_t)z * Hsz + u) * 2) = pack2(ox, oy);
        }
    }
}

// ================= decoder step =================
__device__ __forceinline__ void dec_prefetch(float* sA, float* sB,
    const float* A2, const float* W2, int K, int k0, int m0, int n0, int tid)
{
#pragma unroll
    for (int i = 0; i < 4; i++) {
        int f = tid + i * 256;            // 1024: 128 rows x 8
        int m = f >> 3, c = (f & 7) * 4;
        cpa16(sA + m * STR + c, A2 + ((size_t)(m0 + m) * K + k0) * 2 + c);
    }
#pragma unroll
    for (int i = 0; i < 3; i++) {
        int f = tid + i * 256;            // 768: 96 rows x 8
        int row = f >> 3, c = (f & 7) * 4;
        int g = row >> 5, nn = row & 31;
        cpa16(sB + row * STR + c, W2 + ((size_t)(g * Dsz + n0 + nn) * K + k0) * 2 + c);
    }
}

#define DEC_COMPUTE(Asb, Bsb, ACCN)                                              \
    _Pragma("unroll") for (int kk = 0; kk < KB; kk += 8) {                       \
        uint32_t ah[2][4], al[2][4];                                             \
        LOAD_A_FRAG(Asb, ah, al)                                                 \
        _Pragma("unroll") for (int g = 0; g < 3; g++) {                          \
            _Pragma("unroll") for (int nf = 0; nf < 2; nf++) {                   \
                int nb = g * 32 + wn * 16 + nf * 8 + r;                          \
                uint32_t bh[2], bl[2];                                           \
                LOAD_B_FRAG(Bsb, nb, bh, bl)                                     \
                _Pragma("unroll") for (int mf = 0; mf < 2; mf++) {               \
                    float* cc = (g == 0) ? accR[mf][nf]                          \
                              : (g == 1) ? accZ[mf][nf] : (ACCN)[mf][nf];        \
                    mma8(cc, ah[mf], bh);                                        \
                    mma8(cc, ah[mf], bl);                                        \
                    mma8(cc, al[mf], bh);                                        \
                }                                                                \
            }                                                                    \
        }                                                                        \
    }

#define DEC_PIPE(APTR, KDIM, WPTR, ACCN)                                         \
    {                                                                            \
        int nstg = (KDIM) / KB;                                                  \
        dec_prefetch(sA, sB, (APTR), (WPTR), (KDIM), 0, m0, n0, tid);            \
        CPA_COMMIT;                                                              \
        for (int st = 0; st < nstg; st++) {                                      \
            float* Asb = sA + (st & 1) * (128 * STR);                            \
            float* Bsb = sB + (st & 1) * (96 * STR);                             \
            if (st + 1 < nstg) {                                                 \
                dec_prefetch(sA + ((st + 1) & 1) * (128 * STR),                  \
                             sB + ((st + 1) & 1) * (96 * STR),                   \
                             (APTR), (WPTR), (KDIM), (st + 1) * KB, m0, n0, tid);\
                CPA_COMMIT; CPA_WAIT1;                                           \
            } else { CPA_WAIT0; }                                                \
            __syncthreads();                                                     \
            DEC_COMPUTE(Asb, Bsb, ACCN)                                          \
            __syncthreads();                                                     \
        }                                                                        \
    }

__global__ __launch_bounds__(256) void dec_step_mma(
    const float* __restrict__ HinP, const float* __restrict__ HinI,
    float* __restrict__ HoutP, float* __restrict__ HoutI,
    const float* __restrict__ bih, const float* __restrict__ bhh,
    float* __restrict__ dech, int t)
{
    extern __shared__ float smem[];
    float* sA = smem;                      // 2 x 128 x STR
    float* sB = smem + 2 * 128 * STR;      // 2 x 96 x STR
    int tid = threadIdx.x, lane = tid & 31, wid = tid >> 5;
    int wm = wid & 3, wn = wid >> 2;
    int m0 = blockIdx.y * 128, n0 = blockIdx.x * 32;
    int r = lane >> 2, cq = lane & 3;
    float accR[2][2][4] = {}, accZ[2][2][4] = {}, accN1[2][2][4] = {}, accN2[2][2][4] = {};

    if (t > 0) {
        DEC_PIPE(g_PII, Psz, g_WihDecI, accN1)
    }
    DEC_PIPE(HinI, Dsz, g_WhhDecI, accN2)

    // GRU pointwise + writes
#pragma unroll
    for (int nf = 0; nf < 2; nf++) {
        int u = n0 + wn * 16 + nf * 8 + 2 * cq;
        float2 biR = *(const float2*)(bih + u);
        float2 biZ = *(const float2*)(bih + Dsz + u);
        float2 biN = *(const float2*)(bih + 2 * Dsz + u);
        float2 bhR = *(const float2*)(bhh + u);
        float2 bhZ = *(const float2*)(bhh + Dsz + u);
        float2 bhN = *(const float2*)(bhh + 2 * Dsz + u);
#pragma unroll
        for (int mf = 0; mf < 2; mf++) {
#pragma unroll
            for (int half = 0; half < 2; half++) {
                int m = m0 + wm * 32 + mf * 16 + r + half * 8;
                int b = m & (Bsz - 1);
                int s = m >> 9;
                float2 hold = *(const float2*)(HinP + (size_t)m * Dsz + u);
                int c0 = half * 2;
                float rx = sigmf(accR[mf][nf][c0 + 0] + biR.x + bhR.x);
                float ry = sigmf(accR[mf][nf][c0 + 1] + biR.y + bhR.y);
                float zx = sigmf(accZ[mf][nf][c0 + 0] + biZ.x + bhZ.x);
                float zy = sigmf(accZ[mf][nf][c0 + 1] + biZ.y + bhZ.y);
                float nx = tanhf(accN1[mf][nf][c0 + 0] + biN.x + rx * (accN2[mf][nf][c0 + 0] + bhN.x));
                float ny = tanhf(accN1[mf][nf][c0 + 1] + biN.y + ry * (accN2[mf][nf][c0 + 1] + bhN.y));
                float ox = nx + zx * (hold.x - nx);
                float oy = ny + zy * (hold.y - ny);
                *(float2*)(HoutP + (size_t)m * Dsz + u) = make_float2(ox, oy);
                *(float4*)(HoutI + ((size_t)m * Dsz + u) * 2) = pack2(ox, oy);
                *(float2*)(dech + (((size_t)b * Ssz + s) * Tsz + t) * Dsz + u) = make_float2(ox, oy);
            }
        }
    }
}

// ---------------- out = tanh(h @ W_h2p + b), N = 4 ----------------
__global__ void out_kernel(const float* __restrict__ Hcur,
                           const float* __restrict__ W, const float* __restrict__ bias,
                           float* __restrict__ preds, int t)
{
    int gtid = blockIdx.x * blockDim.x + threadIdx.x;
    int warp = gtid >> 5;
    int lane = threadIdx.x & 31;
    if (warp >= NROWS) return;
    const float* h = Hcur + (size_t)warp * Dsz;
    float ax = 0.f, ay = 0.f, az = 0.f, aw = 0.f;
    for (int d = lane; d < Dsz; d += 32) {
        float hv = h[d];
        float4 w = *(const float4*)(W + (size_t)d * 4);
        ax = fmaf(hv, w.x, ax); ay = fmaf(hv, w.y, ay);
        az = fmaf(hv, w.z, az); aw = fmaf(hv, w.w, aw);
    }
#pragma unroll
    for (int o = 16; o > 0; o >>= 1) {
        ax += __shfl_xor_sync(0xFFFFFFFFu, ax, o);
        ay += __shfl_xor_sync(0xFFFFFFFFu, ay, o);
        az += __shfl_xor_sync(0xFFFFFFFFu, az, o);
        aw += __shfl_xor_sync(0xFFFFFFFFu, aw, o);
    }
    if (lane == 0) {
        int b = warp & (Bsz - 1);
        int s = warp >> 9;
        float4 o;
        o.x = tanhf(ax + bias[0]);
        o.y = tanhf(ay + bias[1]);
        o.z = tanhf(az + bias[2]);
        o.w = tanhf(aw + bias[3]);
        *(float4*)(preds + (((size_t)b * Ssz + s) * Tsz + t) * 4) = o;
    }
}

// ---------------- host ----------------
#define GEMM_SMEM ((2*128*STR + 2*64*STR) * (int)sizeof(float))   // 61440
#define ENC_SMEM  ((2*64*STR  + 2*96*STR) * (int)sizeof(float))   // 51200
#define DEC_SMEM  ((2*128*STR + 2*96*STR) * (int)sizeof(float))   // 71680

extern "C" void kernel_launch(void* const* d_in, const int* in_sizes, int n_in,
                              void* d_out, int out_size)
{
    const float* box      = (const float*)d_in[0];
    const float* dm       = (const float*)d_in[1];
    const float* Wbe      = (const float*)d_in[2];
    const float* bbe      = (const float*)d_in[3];
    const float* Wde      = (const float*)d_in[4];
    const float* bde      = (const float*)d_in[5];
    const float* Wih_box  = (const float*)d_in[6];
    const float* Whh_box  = (const float*)d_in[7];
    const float* bih_box  = (const float*)d_in[8];
    const float* bhh_box  = (const float*)d_in[9];
    const float* Wih_dm   = (const float*)d_in[10];
    const float* Whh_dm   = (const float*)d_in[11];
    const float* bih_dm   = (const float*)d_in[12];
    const float* bhh_dm   = (const float*)d_in[13];
    const float* Wih_dec  = (const float*)d_in[14];
    const float* Whh_dec  = (const float*)d_in[15];
    const float* bih_dec  = (const float*)d_in[16];
    const float* bhh_dec  = (const float*)d_in[17];
    const float* W_h2pi   = (const float*)d_in[18];
    const float* b_h2pi   = (const float*)d_in[19];
    const float* W_h2p    = (const float*)d_in[20];
    const float* b_h2p    = (const float*)d_in[21];

    float* preds = (float*)d_out;                                      // [B,S,T,4]
    float* dech  = (float*)d_out + (size_t)Bsz * Ssz * Tsz * PDsz;     // [B,S,T,D]

    void *p;
    float *embI0, *embI1, *gi0, *gi1, *H0, *H1, *HI0, *HI1, *PII, *hbufI;
    float *WihI0, *WihI1, *WhhI0, *WhhI1, *WihDecI, *WhhDecI, *WpiTI;
    cudaGetSymbolAddress(&p, g_embI);   embI0 = (float*)p; embI1 = embI0 + (size_t)NROWS*Esz*2;
    cudaGetSymbolAddress(&p, g_gi);     gi0 = (float*)p; gi1 = gi0 + (size_t)NROWS*G3H;
    cudaGetSymbolAddress(&p, g_hbufI);  hbufI = (float*)p;
    cudaGetSymbolAddress(&p, g_H);      H0 = (float*)p; H1 = H0 + (size_t)NROWS*Dsz;
    cudaGetSymbolAddress(&p, g_HI);     HI0 = (float*)p; HI1 = HI0 + (size_t)NROWS*Dsz*2;
    cudaGetSymbolAddress(&p, g_PII);    PII = (float*)p;
    cudaGetSymbolAddress(&p, g_WihI);   WihI0 = (float*)p; WihI1 = WihI0 + (size_t)G3H*Esz*2;
    cudaGetSymbolAddress(&p, g_WhhI);   WhhI0 = (float*)p; WhhI1 = WhhI0 + (size_t)G3H*Hsz*2;
    cudaGetSymbolAddress(&p, g_WihDecI); WihDecI = (float*)p;
    cudaGetSymbolAddress(&p, g_WhhDecI); WhhDecI = (float*)p;
    cudaGetSymbolAddress(&p, g_WpiTI);   WpiTI = (float*)p;

    cudaFuncSetAttribute(gemm_nt_pipe<0>, cudaFuncAttributeMaxDynamicSharedMemorySize, GEMM_SMEM);
    cudaFuncSetAttribute(gemm_nt_pipe<1>, cudaFuncAttributeMaxDynamicSharedMemorySize, GEMM_SMEM);
    cudaFuncSetAttribute(enc_step_mma,    cudaFuncAttributeMaxDynamicSharedMemorySize, ENC_SMEM);
    cudaFuncSetAttribute(dec_step_mma,    cudaFuncAttributeMaxDynamicSharedMemorySize, DEC_SMEM);

    // zero initial encoder hiddens (interleaved planes)
    cudaMemsetAsync(hbufI, 0, sizeof(float) * 2 * 2 * (size_t)Bsz * Hsz * 2);

    // one-time weight splits (cheap elementwise)
    {
        int n1 = G3H * Esz;   // Wih enc
        split_kernel<<<(n1 + 255) / 256, 256>>>(Wih_box, WihI0, n1);
        split_kernel<<<(n1 + 255) / 256, 256>>>(Wih_dm,  WihI1, n1);
        int n2 = G3H * Hsz;   // Whh enc
        split_kernel<<<(n2 + 255) / 256, 256>>>(Whh_box, WhhI0, n2);
        split_kernel<<<(n2 + 255) / 256, 256>>>(Whh_dm,  WhhI1, n2);
        int n3 = G3D * Psz;
        split_kernel<<<(n3 + 255) / 256, 256>>>(Wih_dec, WihDecI, n3);
        int n4 = G3D * Dsz;
        split_kernel<<<(n4 + 255) / 256, 256>>>(Whh_dec, WhhDecI, n4);
        dim3 tg(Psz / 32, Dsz / 32);
        transpose_split_kernel<<<tg, dim3(32, 8)>>>(W_h2pi, WpiTI);
    }
    // embeddings (interleaved out)
    {
        dim3 grid((NROWS * Esz + 255) / 256, 2);
        embed_kernel<<<grid, 256>>>(box, dm, Wbe, bbe, Wde, bde);
    }
    // encoder input gates: gi = emb @ Wih^T + bih (plain out)
    {
        dim3 grid(G3H / 64, NROWS / 128);
        gemm_nt_pipe<0><<<grid, 256, GEMM_SMEM>>>(embI0, Esz, WihI0, bih_box, gi0, G3H);
        gemm_nt_pipe<0><<<grid, 256, GEMM_SMEM>>>(embI1, Esz, WihI1, bih_dm,  gi1, G3H);
    }
    // encoder recurrence
    for (int s = 0; s < Ssz; s++) {
        dim3 grid(Hsz / 32, Bsz / 64, 2);
        enc_step_mma<<<grid, 256, ENC_SMEM>>>(s, s & 1, bhh_box, bhh_dm, H0, HI0);
    }
    // decoder: 10 sequential steps at batch 5120
    for (int t = 0; t < Tsz; t++) {
        float* hinP  = (t & 1) ? H1 : H0;
        float* hinI  = (t & 1) ? HI1 : HI0;
        float* houtP = (t & 1) ? H0 : H1;
        float* houtI = (t & 1) ? HI0 : HI1;
        {
            dim3 grid(Dsz / 32, NROWS / 128);
            dec_step_mma<<<grid, 256, DEC_SMEM>>>(hinP, hinI, houtP, houtI,
                                                  bih_dec, bhh_dec, dech, t);
        }
        if (t < Tsz - 1) {
            dim3 grid(Psz / 64, NROWS / 128);
            gemm_nt_pipe<1><<<grid, 256, GEMM_SMEM>>>(houtI, Dsz, WpiTI, b_h2pi, PII, Psz);
        }
        out_kernel<<<(NROWS * 32 + 255) / 256, 256>>>(houtP, W_h2p, b_h2p, preds, t);
    }
}